// round 1
// baseline (speedup 1.0000x reference)
#include <cuda_runtime.h>

#define DIM   768
#define POOL  20
#define TOPK  9
#define NVEC  6            // float4 chunks per lane: 768 / 4 / 32

// Scratch (allocation-free): normalized keys for the selected layer,
// per-row sim sums for rows 0..19, and topk index histogram.
__device__ float        g_kn[POOL * DIM];
__device__ float        g_rowsum[POOL];
__device__ unsigned int g_count[POOL];

// ---------------------------------------------------------------------------
// prep: normalize keys[layer] -> g_kn, zero accumulators. 20 blocks x 256.
// ---------------------------------------------------------------------------
__global__ void prep_kernel(const float* __restrict__ keys,
                            const int*   __restrict__ layer)
{
    const int r = blockIdx.x;
    const float* krow = keys + ((size_t)(*layer) * POOL + r) * DIM;

    float ss = 0.f;
    for (int i = threadIdx.x; i < DIM; i += blockDim.x) {
        float v = krow[i];
        ss += v * v;
    }
    __shared__ float red[32];
    const int lane = threadIdx.x & 31;
    const int w    = threadIdx.x >> 5;
    #pragma unroll
    for (int off = 16; off; off >>= 1)
        ss += __shfl_xor_sync(0xffffffffu, ss, off);
    if (lane == 0) red[w] = ss;
    __syncthreads();
    const int nw = blockDim.x >> 5;
    if (w == 0) {
        float v = (lane < nw) ? red[lane] : 0.f;
        #pragma unroll
        for (int off = 16; off; off >>= 1)
            v += __shfl_xor_sync(0xffffffffu, v, off);
        if (lane == 0) red[0] = v;
    }
    __syncthreads();

    const float inv = 1.f / fmaxf(sqrtf(red[0]), 1e-12f);
    for (int i = threadIdx.x; i < DIM; i += blockDim.x)
        g_kn[r * DIM + i] = krow[i] * inv;

    if (r == 0 && threadIdx.x < POOL) {
        g_count[threadIdx.x]  = 0u;
        g_rowsum[threadIdx.x] = 0.f;
    }
}

// ---------------------------------------------------------------------------
// main: one warp per batch row. 256 threads -> 8 rows per block.
// ---------------------------------------------------------------------------
__global__ void __launch_bounds__(256)
pool_main(const float* __restrict__ x,
          const float* __restrict__ prompts,
          const int*   __restrict__ layer,
          float*       __restrict__ out,
          int B)
{
    __shared__ unsigned int s_count[POOL];
    if (threadIdx.x < POOL) s_count[threadIdx.x] = 0u;
    __syncthreads();

    const int warp = threadIdx.x >> 5;
    const int lane = threadIdx.x & 31;
    const int row  = blockIdx.x * 8 + warp;

    if (row < B) {
        const float4* __restrict__ xr  = (const float4*)(x + (size_t)row * DIM);
        const float4* __restrict__ knv = (const float4*)g_kn;

        float sims[POOL];
        #pragma unroll
        for (int j = 0; j < POOL; j++) sims[j] = 0.f;
        float ss = 0.f;

        #pragma unroll
        for (int i = 0; i < NVEC; i++) {
            const float4 xv = __ldg(xr + lane + 32 * i);
            ss += xv.x * xv.x + xv.y * xv.y + xv.z * xv.z + xv.w * xv.w;
            #pragma unroll
            for (int j = 0; j < POOL; j++) {
                const float4 kv = __ldg(knv + j * (DIM / 4) + lane + 32 * i);
                sims[j] += xv.x * kv.x + xv.y * kv.y + xv.z * kv.z + xv.w * kv.w;
            }
        }

        // butterfly reduce: all lanes end up with the full 20-vector + |x|^2
        #pragma unroll
        for (int off = 16; off; off >>= 1) {
            ss += __shfl_xor_sync(0xffffffffu, ss, off);
            #pragma unroll
            for (int j = 0; j < POOL; j++)
                sims[j] += __shfl_xor_sync(0xffffffffu, sims[j], off);
        }

        const float inv = 1.f / fmaxf(sqrtf(ss), 1e-12f);
        #pragma unroll
        for (int j = 0; j < POOL; j++) sims[j] *= inv;

        // dist bookkeeping: row sums for sim rows 0..19
        if (row < POOL && lane == 0) {
            float rs = 0.f;
            #pragma unroll
            for (int j = 0; j < POOL; j++) rs += sims[j];
            g_rowsum[row] = rs;
        }

        // iterative top-9 (descending, ties -> smaller index, matches lax.top_k).
        // Fully unrolled with predicated marking: no dynamic register indexing.
        int idx[TOPK];
        #pragma unroll
        for (int t = 0; t < TOPK; t++) {
            float best = -3.4e38f;
            int   bj   = 0;
            #pragma unroll
            for (int j = 0; j < POOL; j++)
                if (sims[j] > best) { best = sims[j]; bj = j; }
            idx[t] = bj;
            #pragma unroll
            for (int j = 0; j < POOL; j++)
                if (j == bj) sims[j] = -3.4e38f;
        }

        if (lane == 0) {
            #pragma unroll
            for (int t = 0; t < TOPK; t++)
                atomicAdd(&s_count[idx[t]], 1u);
        }

        // gather: copy 9 prompt rows (768 f32 each) -> out[row]
        const float4* __restrict__ pbase =
            (const float4*)(prompts + (size_t)(*layer) * POOL * DIM);
        float4* __restrict__ orow = (float4*)out + (size_t)row * (TOPK * DIM / 4);
        #pragma unroll
        for (int t = 0; t < TOPK; t++) {
            const float4* pr = pbase + idx[t] * (DIM / 4);
            #pragma unroll
            for (int i = 0; i < NVEC; i++)
                orow[t * (DIM / 4) + lane + 32 * i] = __ldg(pr + lane + 32 * i);
        }
    }

    __syncthreads();
    if (threadIdx.x < POOL)
        atomicAdd(&g_count[threadIdx.x], s_count[threadIdx.x]);
}

// ---------------------------------------------------------------------------
// finalize: dist = 1 - sum_r count[r]*rowsum[r] / (B*TOPK*POOL)
// ---------------------------------------------------------------------------
__global__ void finalize_kernel(float* __restrict__ out,
                                long long total, long long out_size, int B)
{
    double s = 0.0;
    #pragma unroll
    for (int r = 0; r < POOL; r++)
        s += (double)g_count[r] * (double)g_rowsum[r];
    const float dist = (float)(1.0 - s / ((double)B * TOPK * POOL));
    for (long long i = total + threadIdx.x; i < out_size; i += blockDim.x)
        out[i] = dist;
}

extern "C" void kernel_launch(void* const* d_in, const int* in_sizes, int n_in,
                              void* d_out, int out_size)
{
    const float* x       = (const float*)d_in[0];
    const float* keys    = (const float*)d_in[1];
    const float* prompts = (const float*)d_in[2];
    const int*   layer   = (const int*)d_in[3];

    const int B = in_sizes[0] / DIM;
    const long long total = (long long)B * TOPK * DIM;

    prep_kernel<<<POOL, 256>>>(keys, layer);
    pool_main<<<(B + 7) / 8, 256>>>(x, prompts, layer, (float*)d_out, B);
    finalize_kernel<<<1, 32>>>((float*)d_out, total, (long long)out_size, B);
}

// round 2
// speedup vs baseline: 1.0120x; 1.0120x over previous
#include <cuda_runtime.h>

#define DIM   768
#define POOL  20
#define TOPK  9
#define NVEC  6            // float4 chunks per lane: 768 / 4 / 32

// Scratch (allocation-free): normalized keys for the selected layer,
// per-row sim sums for rows 0..19, and topk index histogram.
__device__ float        g_kn[POOL * DIM];
__device__ float        g_rowsum[POOL];
__device__ unsigned int g_count[POOL];

// ---------------------------------------------------------------------------
// prep: normalize keys[layer] -> g_kn, zero accumulators. 20 blocks x 256.
// ---------------------------------------------------------------------------
__global__ void prep_kernel(const float* __restrict__ keys,
                            const int*   __restrict__ layer)
{
    const int r = blockIdx.x;
    const float* krow = keys + ((size_t)(*layer) * POOL + r) * DIM;

    float ss = 0.f;
    for (int i = threadIdx.x; i < DIM; i += blockDim.x) {
        float v = krow[i];
        ss += v * v;
    }
    __shared__ float red[32];
    const int lane = threadIdx.x & 31;
    const int w    = threadIdx.x >> 5;
    #pragma unroll
    for (int off = 16; off; off >>= 1)
        ss += __shfl_xor_sync(0xffffffffu, ss, off);
    if (lane == 0) red[w] = ss;
    __syncthreads();
    const int nw = blockDim.x >> 5;
    if (w == 0) {
        float v = (lane < nw) ? red[lane] : 0.f;
        #pragma unroll
        for (int off = 16; off; off >>= 1)
            v += __shfl_xor_sync(0xffffffffu, v, off);
        if (lane == 0) red[0] = v;
    }
    __syncthreads();

    const float inv = 1.f / fmaxf(sqrtf(red[0]), 1e-12f);
    for (int i = threadIdx.x; i < DIM; i += blockDim.x)
        g_kn[r * DIM + i] = krow[i] * inv;

    if (r == 0 && threadIdx.x < POOL) {
        g_count[threadIdx.x]  = 0u;
        g_rowsum[threadIdx.x] = 0.f;
    }
}

// ---------------------------------------------------------------------------
// main: one warp per batch row. 256 threads -> 8 rows per block.
// ---------------------------------------------------------------------------
__global__ void __launch_bounds__(256)
pool_main(const float* __restrict__ x,
          const float* __restrict__ prompts,
          const int*   __restrict__ layer,
          float*       __restrict__ out,
          int B)
{
    __shared__ unsigned int s_count[POOL];
    if (threadIdx.x < POOL) s_count[threadIdx.x] = 0u;
    __syncthreads();

    const int warp = threadIdx.x >> 5;
    const int lane = threadIdx.x & 31;
    const int row  = blockIdx.x * 8 + warp;

    if (row < B) {
        const float4* __restrict__ xr  = (const float4*)(x + (size_t)row * DIM);
        const float4* __restrict__ knv = (const float4*)g_kn;

        float sims[POOL];
        #pragma unroll
        for (int j = 0; j < POOL; j++) sims[j] = 0.f;
        float ss = 0.f;

        #pragma unroll
        for (int i = 0; i < NVEC; i++) {
            const float4 xv = __ldg(xr + lane + 32 * i);
            ss += xv.x * xv.x + xv.y * xv.y + xv.z * xv.z + xv.w * xv.w;
            #pragma unroll
            for (int j = 0; j < POOL; j++) {
                const float4 kv = __ldg(knv + j * (DIM / 4) + lane + 32 * i);
                sims[j] += xv.x * kv.x + xv.y * kv.y + xv.z * kv.z + xv.w * kv.w;
            }
        }

        // butterfly reduce: all lanes end up with the full 20-vector + |x|^2
        #pragma unroll
        for (int off = 16; off; off >>= 1) {
            ss += __shfl_xor_sync(0xffffffffu, ss, off);
            #pragma unroll
            for (int j = 0; j < POOL; j++)
                sims[j] += __shfl_xor_sync(0xffffffffu, sims[j], off);
        }

        const float inv = 1.f / fmaxf(sqrtf(ss), 1e-12f);
        #pragma unroll
        for (int j = 0; j < POOL; j++) sims[j] *= inv;

        // dist bookkeeping: row sums for sim rows 0..19
        if (row < POOL && lane == 0) {
            float rs = 0.f;
            #pragma unroll
            for (int j = 0; j < POOL; j++) rs += sims[j];
            g_rowsum[row] = rs;
        }

        // iterative top-9 (descending, ties -> smaller index, matches lax.top_k).
        // Fully unrolled with predicated marking: no dynamic register indexing.
        int idx[TOPK];
        #pragma unroll
        for (int t = 0; t < TOPK; t++) {
            float best = -3.4e38f;
            int   bj   = 0;
            #pragma unroll
            for (int j = 0; j < POOL; j++)
                if (sims[j] > best) { best = sims[j]; bj = j; }
            idx[t] = bj;
            #pragma unroll
            for (int j = 0; j < POOL; j++)
                if (j == bj) sims[j] = -3.4e38f;
        }

        if (lane == 0) {
            #pragma unroll
            for (int t = 0; t < TOPK; t++)
                atomicAdd(&s_count[idx[t]], 1u);
        }

        // gather: copy 9 prompt rows (768 f32 each) -> out[row]
        const float4* __restrict__ pbase =
            (const float4*)(prompts + (size_t)(*layer) * POOL * DIM);
        float4* __restrict__ orow = (float4*)out + (size_t)row * (TOPK * DIM / 4);
        #pragma unroll
        for (int t = 0; t < TOPK; t++) {
            const float4* pr = pbase + idx[t] * (DIM / 4);
            #pragma unroll
            for (int i = 0; i < NVEC; i++)
                orow[t * (DIM / 4) + lane + 32 * i] = __ldg(pr + lane + 32 * i);
        }
    }

    __syncthreads();
    if (threadIdx.x < POOL)
        atomicAdd(&g_count[threadIdx.x], s_count[threadIdx.x]);
}

// ---------------------------------------------------------------------------
// finalize: dist = 1 - sum_r count[r]*rowsum[r] / (B*TOPK*POOL)
// ---------------------------------------------------------------------------
__global__ void finalize_kernel(float* __restrict__ out,
                                long long total, long long out_size, int B)
{
    double s = 0.0;
    #pragma unroll
    for (int r = 0; r < POOL; r++)
        s += (double)g_count[r] * (double)g_rowsum[r];
    const float dist = (float)(1.0 - s / ((double)B * TOPK * POOL));
    for (long long i = total + threadIdx.x; i < out_size; i += blockDim.x)
        out[i] = dist;
}

extern "C" void kernel_launch(void* const* d_in, const int* in_sizes, int n_in,
                              void* d_out, int out_size)
{
    const float* x       = (const float*)d_in[0];
    const float* keys    = (const float*)d_in[1];
    const float* prompts = (const float*)d_in[2];
    const int*   layer   = (const int*)d_in[3];

    const int B = in_sizes[0] / DIM;
    const long long total = (long long)B * TOPK * DIM;

    prep_kernel<<<POOL, 256>>>(keys, layer);
    pool_main<<<(B + 7) / 8, 256>>>(x, prompts, layer, (float*)d_out, B);
    finalize_kernel<<<1, 32>>>((float*)d_out, total, (long long)out_size, B);
}

// round 3
// speedup vs baseline: 1.3471x; 1.3311x over previous
#include <cuda_runtime.h>

#define DIM   768
#define POOL  20
#define TOPK  9
#define NVEC  6                 // float4 chunks per lane: 768 / 4 / 32
#define WARPS 8
#define ROWS_PER_WARP  2
#define ROWS_PER_BLOCK (WARPS * ROWS_PER_WARP)   // 16

// Allocation-free scratch
__device__ float        g_kn[POOL * DIM];
__device__ float        g_rowsum[POOL];
__device__ unsigned int g_count[POOL];

// ---------------------------------------------------------------------------
// prep: 1 block x 640 threads. Warp w normalizes key row w (shuffle-only).
// ---------------------------------------------------------------------------
__global__ void prep_kernel(const float* __restrict__ keys,
                            const int*   __restrict__ layer)
{
    const int w    = threadIdx.x >> 5;
    const int lane = threadIdx.x & 31;

    if (w < POOL) {
        const float* __restrict__ krow =
            keys + ((size_t)(*layer) * POOL + w) * DIM;
        float ss = 0.f;
        #pragma unroll
        for (int i = 0; i < DIM / 32; i++) {
            float v = __ldg(krow + lane + 32 * i);
            ss += v * v;
        }
        #pragma unroll
        for (int off = 16; off; off >>= 1)
            ss += __shfl_xor_sync(0xffffffffu, ss, off);
        const float inv = 1.f / fmaxf(sqrtf(ss), 1e-12f);
        #pragma unroll
        for (int i = 0; i < DIM / 32; i++)
            g_kn[w * DIM + lane + 32 * i] = __ldg(krow + lane + 32 * i) * inv;
    }
    if (threadIdx.x < POOL) {
        g_count[threadIdx.x]  = 0u;
        g_rowsum[threadIdx.x] = 0.f;
    }
}

// ---------------------------------------------------------------------------
// main: one warp handles TWO batch rows (shares every key load across both).
// ---------------------------------------------------------------------------
__global__ void __launch_bounds__(256)
pool_main(const float* __restrict__ x,
          const float* __restrict__ prompts,
          const int*   __restrict__ layer,
          float*       __restrict__ out,
          int B)
{
    __shared__ unsigned int s_count[POOL];
    if (threadIdx.x < POOL) s_count[threadIdx.x] = 0u;
    __syncthreads();

    const int warp = threadIdx.x >> 5;
    const int lane = threadIdx.x & 31;
    const int r0   = blockIdx.x * ROWS_PER_BLOCK + warp * ROWS_PER_WARP;
    const int r1   = r0 + 1;

    if (r1 < B) {
        const float4* __restrict__ xr0 = (const float4*)(x + (size_t)r0 * DIM);
        const float4* __restrict__ xr1 = (const float4*)(x + (size_t)r1 * DIM);
        const float4* __restrict__ knv = (const float4*)g_kn;

        float s0[POOL], s1[POOL];
        #pragma unroll
        for (int j = 0; j < POOL; j++) { s0[j] = 0.f; s1[j] = 0.f; }
        float ss0 = 0.f, ss1 = 0.f;

        #pragma unroll
        for (int i = 0; i < NVEC; i++) {
            // streaming loads: evict-first, keep keys/prompts resident in L1
            const float4 xv0 = __ldcs(xr0 + lane + 32 * i);
            const float4 xv1 = __ldcs(xr1 + lane + 32 * i);
            ss0 += xv0.x * xv0.x + xv0.y * xv0.y + xv0.z * xv0.z + xv0.w * xv0.w;
            ss1 += xv1.x * xv1.x + xv1.y * xv1.y + xv1.z * xv1.z + xv1.w * xv1.w;
            #pragma unroll
            for (int j = 0; j < POOL; j++) {
                const float4 kv = __ldg(knv + j * (DIM / 4) + lane + 32 * i);
                s0[j] += xv0.x * kv.x + xv0.y * kv.y + xv0.z * kv.z + xv0.w * kv.w;
                s1[j] += xv1.x * kv.x + xv1.y * kv.y + xv1.z * kv.z + xv1.w * kv.w;
            }
        }

        // butterfly reduce all 42 accumulators
        #pragma unroll
        for (int off = 16; off; off >>= 1) {
            ss0 += __shfl_xor_sync(0xffffffffu, ss0, off);
            ss1 += __shfl_xor_sync(0xffffffffu, ss1, off);
            #pragma unroll
            for (int j = 0; j < POOL; j++) {
                s0[j] += __shfl_xor_sync(0xffffffffu, s0[j], off);
                s1[j] += __shfl_xor_sync(0xffffffffu, s1[j], off);
            }
        }

        const float inv0 = 1.f / fmaxf(sqrtf(ss0), 1e-12f);
        const float inv1 = 1.f / fmaxf(sqrtf(ss1), 1e-12f);
        #pragma unroll
        for (int j = 0; j < POOL; j++) { s0[j] *= inv0; s1[j] *= inv1; }

        // dist bookkeeping: pool-sums of sim rows 0..19
        if (lane == 0) {
            if (r0 < POOL) {
                float rs = 0.f;
                #pragma unroll
                for (int j = 0; j < POOL; j++) rs += s0[j];
                g_rowsum[r0] = rs;
            }
            if (r1 < POOL) {
                float rs = 0.f;
                #pragma unroll
                for (int j = 0; j < POOL; j++) rs += s1[j];
                g_rowsum[r1] = rs;
            }
        }

        // iterative top-9 (strict '>' => lower index wins ties, matches lax.top_k)
        int idx0[TOPK], idx1[TOPK];
        #pragma unroll
        for (int t = 0; t < TOPK; t++) {
            float best = -3.4e38f; int bj = 0;
            #pragma unroll
            for (int j = 0; j < POOL; j++)
                if (s0[j] > best) { best = s0[j]; bj = j; }
            idx0[t] = bj;
            #pragma unroll
            for (int j = 0; j < POOL; j++)
                if (j == bj) s0[j] = -3.4e38f;
        }
        #pragma unroll
        for (int t = 0; t < TOPK; t++) {
            float best = -3.4e38f; int bj = 0;
            #pragma unroll
            for (int j = 0; j < POOL; j++)
                if (s1[j] > best) { best = s1[j]; bj = j; }
            idx1[t] = bj;
            #pragma unroll
            for (int j = 0; j < POOL; j++)
                if (j == bj) s1[j] = -3.4e38f;
        }

        if (lane == 0) {
            #pragma unroll
            for (int t = 0; t < TOPK; t++) {
                atomicAdd(&s_count[idx0[t]], 1u);
                atomicAdd(&s_count[idx1[t]], 1u);
            }
        }

        // gather: 18 prompt-row copies, coalesced streaming stores
        const float4* __restrict__ pbase =
            (const float4*)(prompts + (size_t)(*layer) * POOL * DIM);
        float4* __restrict__ o0 = (float4*)out + (size_t)r0 * (TOPK * DIM / 4);
        float4* __restrict__ o1 = (float4*)out + (size_t)r1 * (TOPK * DIM / 4);
        #pragma unroll
        for (int t = 0; t < TOPK; t++) {
            const float4* pr0 = pbase + idx0[t] * (DIM / 4);
            const float4* pr1 = pbase + idx1[t] * (DIM / 4);
            #pragma unroll
            for (int i = 0; i < NVEC; i++) {
                __stcs(o0 + t * (DIM / 4) + lane + 32 * i, __ldg(pr0 + lane + 32 * i));
                __stcs(o1 + t * (DIM / 4) + lane + 32 * i, __ldg(pr1 + lane + 32 * i));
            }
        }
    }

    __syncthreads();
    if (threadIdx.x < POOL)
        atomicAdd(&g_count[threadIdx.x], s_count[threadIdx.x]);
}

// ---------------------------------------------------------------------------
// finalize: dist = 1 - sum_r count[r]*rowsum[r] / (B*TOPK*POOL)
// ---------------------------------------------------------------------------
__global__ void finalize_kernel(float* __restrict__ out,
                                long long total, long long out_size, int B)
{
    double s = 0.0;
    #pragma unroll
    for (int r = 0; r < POOL; r++)
        s += (double)g_count[r] * (double)g_rowsum[r];
    const float dist = (float)(1.0 - s / ((double)B * TOPK * POOL));
    for (long long i = total + threadIdx.x; i < out_size; i += blockDim.x)
        out[i] = dist;
}

extern "C" void kernel_launch(void* const* d_in, const int* in_sizes, int n_in,
                              void* d_out, int out_size)
{
    const float* x       = (const float*)d_in[0];
    const float* keys    = (const float*)d_in[1];
    const float* prompts = (const float*)d_in[2];
    const int*   layer   = (const int*)d_in[3];

    const int B = in_sizes[0] / DIM;
    const long long total = (long long)B * TOPK * DIM;

    prep_kernel<<<1, 640>>>(keys, layer);
    pool_main<<<(B + ROWS_PER_BLOCK - 1) / ROWS_PER_BLOCK, 256>>>(
        x, prompts, layer, (float*)d_out, B);
    finalize_kernel<<<1, 32>>>((float*)d_out, total, (long long)out_size, B);
}